// round 1
// baseline (speedup 1.0000x reference)
#include <cuda_runtime.h>

#define BB 32
#define NVV 8192
#define NEE 65536
#define ELLMAX 48
#define NSUB 8
#define VB 16          // vertex-blocks per batch (NVV / TPB)
#define TPB 512
#define CG_ITERS 20
#define DTf 0.01f
#define KSf 10000.0f
#define C2f 1.0f       // DT*DT*K_SPRING in f64 -> f32 == 1.0f exactly

// ---------------- scratch (static device globals; no runtime allocation) ----
__device__ float4 g_pos[BB*NVV];
__device__ float4 g_x  [BB*NVV];   // doubles as velocity between substeps
__device__ float4 g_r  [BB*NVV];
__device__ float4 g_p  [BB*NVV];
__device__ float4 g_Ap [BB*NVV];
__device__ int    g_cnt[NVV];
__device__ int    g_nbr[ELLMAX*NVV];
__device__ int    g_eid[ELLMAX*NVV];
__device__ float  g_rest[(size_t)BB*ELLMAX*NVV];   // [b][k][v], ~50 MB
__device__ float  g_partA[BB*VB];  // rs partials (ping)
__device__ float  g_partB[BB*VB];  // rs partials (pong)
__device__ float  g_pApP [BB*VB];  // p.Ap partials

// ---------------- helpers ---------------------------------------------------
__device__ __forceinline__ float blockReduce(float v, float* s) {
    int lane = threadIdx.x & 31, w = threadIdx.x >> 5;
    #pragma unroll
    for (int o = 16; o > 0; o >>= 1) v += __shfl_down_sync(0xffffffffu, v, o);
    if (lane == 0) s[w] = v;
    __syncthreads();
    if (threadIdx.x < 16) {
        v = s[threadIdx.x];
        #pragma unroll
        for (int o = 8; o > 0; o >>= 1) v += __shfl_down_sync(0xffffu, v, o);
    }
    return v;   // valid on thread 0
}

// ---------------- setup kernels ---------------------------------------------
__global__ void k_zero_cnt() {
    int v = blockIdx.x * blockDim.x + threadIdx.x;
    if (v < NVV) g_cnt[v] = 0;
}

__global__ void k_init(const float* __restrict__ pos0, const float* __restrict__ vel0) {
    int i = blockIdx.x * blockDim.x + threadIdx.x;   // i = b*NVV + v
    if (i >= BB * NVV) return;
    g_pos[i] = make_float4(pos0[i*3+0], pos0[i*3+1], pos0[i*3+2], 0.f);
    g_x  [i] = make_float4(vel0[i*3+0], vel0[i*3+1], vel0[i*3+2], 0.f);
}

__global__ void k_fill(const int* __restrict__ ei, const int* __restrict__ ej) {
    int e = blockIdx.x * blockDim.x + threadIdx.x;
    if (e >= NEE) return;
    int i = ei[e], j = ej[e];
    int si = atomicAdd(&g_cnt[i], 1);
    if (si < ELLMAX) { g_nbr[si*NVV + i] = j; g_eid[si*NVV + i] = e; }
    int sj = atomicAdd(&g_cnt[j], 1);
    if (sj < ELLMAX) { g_nbr[sj*NVV + j] = i; g_eid[sj*NVV + j] = e; }
}

// sort each vertex's adjacency by (neighbor, edge-id) -> deterministic sums
__global__ void k_sort() {
    int v = blockIdx.x * blockDim.x + threadIdx.x;
    if (v >= NVV) return;
    int d = min(g_cnt[v], ELLMAX);
    long long key[ELLMAX];
    for (int k = 0; k < d; k++)
        key[k] = ((long long)g_nbr[k*NVV + v] << 32) | (unsigned)g_eid[k*NVV + v];
    for (int a = 1; a < d; a++) {
        long long t = key[a]; int b = a - 1;
        while (b >= 0 && key[b] > t) { key[b+1] = key[b]; b--; }
        key[b+1] = t;
    }
    for (int k = 0; k < d; k++) {
        g_nbr[k*NVV + v] = (int)(key[k] >> 32);
        g_eid[k*NVV + v] = (int)(key[k] & 0xffffffffLL);
    }
}

// rest_eff in ELL order: [b][k][v]
__global__ void k_rest(const float* __restrict__ rest_len, const float* __restrict__ act) {
    int v = blockIdx.x * blockDim.x + threadIdx.x;
    int b = blockIdx.y;
    if (v >= NVV) return;
    int d = min(g_cnt[v], ELLMAX);
    for (int k = 0; k < d; k++) {
        int e = g_eid[k*NVV + v];
        g_rest[((size_t)b*ELLMAX + k)*NVV + v] = rest_len[e] * (1.f + act[(size_t)b*NEE + e]);
    }
}

// ---------------- per-substep kernels ---------------------------------------
// force + b-vector; sets r=p=b, x=0; rs0 partials -> g_partA
__global__ void k_force(const float* __restrict__ mass) {
    __shared__ float s[16];
    int v = blockIdx.x * TPB + threadIdx.x;
    int b = blockIdx.y;
    int i = b*NVV + v;
    float4 P = g_pos[i];
    float4 V = g_x[i];            // velocity from previous substep
    float  m = mass[v];
    int    d = min(g_cnt[v], ELLMAX);
    float fx = 0.f, fy = 0.f, fz = 0.f;
    #pragma unroll 4
    for (int k = 0; k < d; k++) {
        int u = g_nbr[k*NVV + v];
        float4 Q = __ldg(&g_pos[b*NVV + u]);
        float dx = P.x - Q.x, dy = P.y - Q.y, dz = P.z - Q.z;
        float l  = sqrtf(dx*dx + dy*dy + dz*dz);
        float rr = g_rest[((size_t)b*ELLMAX + k)*NVV + v];
        float c  = -KSf * (l - rr) / fmaxf(l, 1e-6f);
        fx += c*dx; fy += c*dy; fz += c*dz;
    }
    fy += m * (-9.8f);
    float bx = m*V.x + DTf*fx;
    float by = m*V.y + DTf*fy;
    float bz = m*V.z + DTf*fz;
    float4 B4 = make_float4(bx, by, bz, 0.f);
    g_r[i] = B4;
    g_p[i] = B4;
    g_x[i] = make_float4(0.f, 0.f, 0.f, 0.f);
    float t = blockReduce(bx*bx + by*by + bz*bz, s);
    if (threadIdx.x == 0) g_partA[b*VB + blockIdx.x] = t;
}

// Ap = (m + dt^2 k L) p ; p.Ap partials
__global__ void k_mv(const float* __restrict__ mass) {
    __shared__ float s[16];
    int v = blockIdx.x * TPB + threadIdx.x;
    int b = blockIdx.y;
    int i = b*NVV + v;
    float4 Pv = g_p[i];
    float  m  = mass[v];
    int    d  = min(g_cnt[v], ELLMAX);
    float sx = 0.f, sy = 0.f, sz = 0.f;
    #pragma unroll 4
    for (int k = 0; k < d; k++) {
        int u = g_nbr[k*NVV + v];
        float4 Q = __ldg(&g_p[b*NVV + u]);
        sx += Q.x; sy += Q.y; sz += Q.z;
    }
    float df = (float)d;
    float ax = m*Pv.x + C2f*(df*Pv.x - sx);
    float ay = m*Pv.y + C2f*(df*Pv.y - sy);
    float az = m*Pv.z + C2f*(df*Pv.z - sz);
    g_Ap[i] = make_float4(ax, ay, az, 0.f);
    float t = blockReduce(Pv.x*ax + Pv.y*ay + Pv.z*az, s);
    if (threadIdx.x == 0) g_pApP[b*VB + blockIdx.x] = t;
}

// alpha = rs/(pAp+eps); x += a p; r -= a Ap; rs_new partials
__global__ void k_upd(int parity) {
    __shared__ float s[16];
    __shared__ float s_alpha;
    const float* rsP  = parity ? g_partB : g_partA;
    float*       rsnP = parity ? g_partA : g_partB;
    int v = blockIdx.x * TPB + threadIdx.x;
    int b = blockIdx.y;
    int i = b*NVV + v;
    if (threadIdx.x == 0) {
        float rs = 0.f, pap = 0.f;
        for (int k = 0; k < VB; k++) { rs += rsP[b*VB + k]; pap += g_pApP[b*VB + k]; }
        s_alpha = rs / (pap + 1e-12f);
    }
    __syncthreads();
    float a = s_alpha;
    float4 X = g_x[i], R = g_r[i], Pv = g_p[i], A4 = g_Ap[i];
    X.x += a*Pv.x; X.y += a*Pv.y; X.z += a*Pv.z;
    R.x -= a*A4.x; R.y -= a*A4.y; R.z -= a*A4.z;
    g_x[i] = X;
    g_r[i] = R;
    float t = blockReduce(R.x*R.x + R.y*R.y + R.z*R.z, s);
    if (threadIdx.x == 0) rsnP[b*VB + blockIdx.x] = t;
}

// beta = rs_new/(rs+eps); p = r + beta p
__global__ void k_pfin(int parity) {
    __shared__ float s_beta;
    const float* rsP  = parity ? g_partB : g_partA;   // old rs
    const float* rsnP = parity ? g_partA : g_partB;   // new rs
    int v = blockIdx.x * TPB + threadIdx.x;
    int b = blockIdx.y;
    int i = b*NVV + v;
    if (threadIdx.x == 0) {
        float rs = 0.f, rsn = 0.f;
        for (int k = 0; k < VB; k++) { rs += rsP[b*VB + k]; rsn += rsnP[b*VB + k]; }
        s_beta = rsn / (rs + 1e-12f);
    }
    __syncthreads();
    float bb = s_beta;
    float4 R = g_r[i], Pv = g_p[i];
    Pv.x = R.x + bb*Pv.x;
    Pv.y = R.y + bb*Pv.y;
    Pv.z = R.z + bb*Pv.z;
    g_p[i] = Pv;
}

// pos += dt * v_new; emit trajectory slice (out is [B][NSUB][NV][3])
__global__ void k_pos(float* __restrict__ out, int step) {
    int v = blockIdx.x * TPB + threadIdx.x;
    int b = blockIdx.y;
    int i = b*NVV + v;
    float4 P = g_pos[i];
    float4 V = g_x[i];
    P.x += DTf*V.x; P.y += DTf*V.y; P.z += DTf*V.z;
    g_pos[i] = P;
    size_t o = (((size_t)b*NSUB + step)*NVV + v)*3;
    out[o+0] = P.x; out[o+1] = P.y; out[o+2] = P.z;
}

// ---------------- launch ----------------------------------------------------
extern "C" void kernel_launch(void* const* d_in, const int* in_sizes, int n_in,
                              void* d_out, int out_size) {
    const float* act   = (const float*)d_in[0];
    const float* pos0  = (const float*)d_in[1];
    const float* vel0  = (const float*)d_in[2];
    const float* rlen  = (const float*)d_in[3];
    const float* mass  = (const float*)d_in[4];
    const int*   ei    = (const int*)d_in[5];
    const int*   ej    = (const int*)d_in[6];
    float*       out   = (float*)d_out;

    k_zero_cnt<<<(NVV+255)/256, 256>>>();
    k_init<<<(BB*NVV+255)/256, 256>>>(pos0, vel0);
    k_fill<<<(NEE+255)/256, 256>>>(ei, ej);
    k_sort<<<(NVV+127)/128, 128>>>();
    k_rest<<<dim3(NVV/256, BB), 256>>>(rlen, act);

    dim3 g(VB, BB);
    for (int s = 0; s < NSUB; s++) {
        k_force<<<g, TPB>>>(mass);
        for (int it = 0; it < CG_ITERS; it++) {
            int parity = it & 1;
            k_mv  <<<g, TPB>>>(mass);
            k_upd <<<g, TPB>>>(parity);
            k_pfin<<<g, TPB>>>(parity);
        }
        k_pos<<<g, TPB>>>(out, s);
    }
}

// round 2
// speedup vs baseline: 1.4027x; 1.4027x over previous
#include <cuda_runtime.h>

#define BB 32
#define NVV 8192
#define NEE 65536
#define ELLMAX 48
#define NSUB 8
#define NCTA 8          // CTAs per batch
#define TPB 1024
#define VPC 1024        // vertices per CTA (NVV / NCTA)
#define CG_ITERS 20
#define DTf 0.01f
#define KSf 10000.0f
#define CS (BB*NVV)     // component stride for planar SoA

// ---------------- scratch (static device globals) ---------------------------
__device__ float g_pos[3*CS];
__device__ float g_x  [3*CS];          // velocity between substeps / CG x
__device__ float g_r  [3*CS];
__device__ float g_pb [2][3*CS];       // double-buffered p
__device__ float g_Ap [3*CS];
__device__ int   g_cnt[NVV];
__device__ int   g_deg[NVV];
__device__ int   g_nbr[ELLMAX*NVV];
__device__ int   g_eid[ELLMAX*NVV];
__device__ float g_rest[(size_t)BB*ELLMAX*NVV];   // [b][k][v]
__device__ float g_rs [2][BB][NCTA];   // rs partials, ping/pong by iteration parity
__device__ float g_pAp[BB][NCTA];

// ---------------- helpers ---------------------------------------------------
// 1024-thread block reduce; result valid on thread 0
__device__ __forceinline__ float bred(float v, float* s32) {
    int lane = threadIdx.x & 31, w = threadIdx.x >> 5;
    #pragma unroll
    for (int o = 16; o > 0; o >>= 1) v += __shfl_down_sync(0xffffffffu, v, o);
    if (lane == 0) s32[w] = v;
    __syncthreads();
    if (threadIdx.x < 32) {
        v = s32[threadIdx.x];
        #pragma unroll
        for (int o = 16; o > 0; o >>= 1) v += __shfl_down_sync(0xffffffffu, v, o);
    }
    return v;
}

// ---------------- setup ------------------------------------------------------
__global__ void k_zero_cnt() {
    int v = blockIdx.x * blockDim.x + threadIdx.x;
    if (v < NVV) g_cnt[v] = 0;
}

__global__ void k_init(const float* __restrict__ pos0, const float* __restrict__ vel0) {
    int i = blockIdx.x * blockDim.x + threadIdx.x;   // i = b*NVV + v
    if (i >= CS) return;
    #pragma unroll
    for (int c = 0; c < 3; c++) {
        g_pos[c*CS + i] = pos0[i*3 + c];
        g_x  [c*CS + i] = vel0[i*3 + c];
    }
}

__global__ void k_fill(const int* __restrict__ ei, const int* __restrict__ ej) {
    int e = blockIdx.x * blockDim.x + threadIdx.x;
    if (e >= NEE) return;
    int i = ei[e], j = ej[e];
    int si = atomicAdd(&g_cnt[i], 1);
    if (si < ELLMAX) { g_nbr[si*NVV + i] = j; g_eid[si*NVV + i] = e; }
    int sj = atomicAdd(&g_cnt[j], 1);
    if (sj < ELLMAX) { g_nbr[sj*NVV + j] = i; g_eid[sj*NVV + j] = e; }
}

// deterministic adjacency order per vertex
__global__ void k_sort() {
    int v = blockIdx.x * blockDim.x + threadIdx.x;
    if (v >= NVV) return;
    int d = min(g_cnt[v], ELLMAX);
    g_deg[v] = d;
    long long key[ELLMAX];
    for (int k = 0; k < d; k++)
        key[k] = ((long long)g_nbr[k*NVV + v] << 32) | (unsigned)g_eid[k*NVV + v];
    for (int a = 1; a < d; a++) {
        long long t = key[a]; int b = a - 1;
        while (b >= 0 && key[b] > t) { key[b+1] = key[b]; b--; }
        key[b+1] = t;
    }
    for (int k = 0; k < d; k++) {
        g_nbr[k*NVV + v] = (int)(key[k] >> 32);
        g_eid[k*NVV + v] = (int)(key[k] & 0xffffffffLL);
    }
}

__global__ void k_rest(const float* __restrict__ rest_len, const float* __restrict__ act) {
    int v = blockIdx.x * blockDim.x + threadIdx.x;
    int b = blockIdx.y;
    if (v >= NVV) return;
    int d = g_deg[v];
    for (int k = 0; k < d; k++) {
        int e = g_eid[k*NVV + v];
        g_rest[((size_t)b*ELLMAX + k)*NVV + v] = rest_len[e] * (1.f + act[(size_t)b*NEE + e]);
    }
}

// ---------------- per-substep kernels ---------------------------------------
// Force + b-vector. Stages pos in smem. Sets r=p=b (p -> buffer 0), x=0,
// rs0 partials -> slot 0.
__global__ void __launch_bounds__(TPB, 2) k_force(const float* __restrict__ mass) {
    extern __shared__ float sm[];
    float2* s_xy = (float2*)sm;          // 64 KB
    float*  s_z  = sm + 2*NVV;           // 32 KB
    __shared__ float s32[32];
    int tid = threadIdx.x, cx = blockIdx.x, b = blockIdx.y;
    int base = b*NVV;

    #pragma unroll
    for (int j = 0; j < NCTA; j++) {
        int v = j*TPB + tid;
        s_xy[v] = make_float2(g_pos[base + v], g_pos[CS + base + v]);
        s_z [v] = g_pos[2*CS + base + v];
    }
    __syncthreads();

    int v = cx*VPC + tid;
    int i = base + v;
    float2 Pxy = s_xy[v]; float Pz = s_z[v];
    float m = mass[v];
    int   d = g_deg[v];
    float fx = 0.f, fy = 0.f, fz = 0.f;
    #pragma unroll 4
    for (int k = 0; k < d; k++) {
        int u = g_nbr[k*NVV + v];
        float2 Q = s_xy[u];
        float dx = Pxy.x - Q.x, dy = Pxy.y - Q.y, dz = Pz - s_z[u];
        float l  = sqrtf(dx*dx + dy*dy + dz*dz);
        float rr = g_rest[((size_t)b*ELLMAX + k)*NVV + v];
        float c  = -KSf * (l - rr) / fmaxf(l, 1e-6f);
        fx += c*dx; fy += c*dy; fz += c*dz;
    }
    fy += m * (-9.8f);
    float bx = m*g_x[i]        + DTf*fx;
    float by = m*g_x[CS + i]   + DTf*fy;
    float bz = m*g_x[2*CS + i] + DTf*fz;
    g_r[i] = bx;  g_r[CS+i] = by;  g_r[2*CS+i] = bz;
    g_pb[0][i] = bx;  g_pb[0][CS+i] = by;  g_pb[0][2*CS+i] = bz;
    g_x[i] = 0.f; g_x[CS+i] = 0.f; g_x[2*CS+i] = 0.f;
    float t = bred(bx*bx + by*by + bz*bz, s32);
    if (tid == 0) g_rs[0][b][cx] = t;
}

// Matvec with fused p-update.
// it==0: stage p from buffer 0 (p = r, set by force).
// it>0 : beta = rs_it/rs_{it-1}; stage p_new = r + beta*p_old (read buf prev,
//        write own slice to buf cur). Then Ap = (m + L) p, pAp partials.
__global__ void __launch_bounds__(TPB, 2) k_mv(const float* __restrict__ mass, int it) {
    extern __shared__ float sm[];
    float2* s_xy = (float2*)sm;
    float*  s_z  = sm + 2*NVV;
    __shared__ float s32[32];
    __shared__ float s_beta;
    int tid = threadIdx.x, cx = blockIdx.x, b = blockIdx.y;
    int base = b*NVV;
    int cur = it & 1, prev = cur ^ 1;

    if (it == 0) {
        const float* pb = g_pb[0];
        #pragma unroll
        for (int j = 0; j < NCTA; j++) {
            int v = j*TPB + tid;
            s_xy[v] = make_float2(pb[base + v], pb[CS + base + v]);
            s_z [v] = pb[2*CS + base + v];
        }
    } else {
        if (tid == 0) {
            float rsn = 0.f, rso = 0.f;
            #pragma unroll
            for (int k = 0; k < NCTA; k++) { rsn += g_rs[cur][b][k]; rso += g_rs[prev][b][k]; }
            s_beta = rsn / (rso + 1e-12f);
        }
        __syncthreads();
        float beta = s_beta;
        const float* po = g_pb[prev];
        float*       pn = g_pb[cur];
        #pragma unroll
        for (int j = 0; j < NCTA; j++) {
            int v = j*TPB + tid;
            float px = fmaf(beta, po[base + v],        g_r[base + v]);
            float py = fmaf(beta, po[CS + base + v],   g_r[CS + base + v]);
            float pz = fmaf(beta, po[2*CS + base + v], g_r[2*CS + base + v]);
            s_xy[v] = make_float2(px, py); s_z[v] = pz;
            if (j == cx) {                      // own slice -> global (no race: double buffer)
                pn[base + v] = px; pn[CS + base + v] = py; pn[2*CS + base + v] = pz;
            }
        }
    }
    __syncthreads();

    int v = cx*VPC + tid;
    int i = base + v;
    int d = g_deg[v];
    float sx = 0.f, sy = 0.f, sz = 0.f;
    #pragma unroll 4
    for (int k = 0; k < d; k++) {
        int u = g_nbr[k*NVV + v];
        float2 q = s_xy[u];
        sx += q.x; sy += q.y; sz += s_z[u];
    }
    float2 pxy = s_xy[v]; float pz = s_z[v];
    float m = mass[v];
    float df = (float)d;
    float ax = m*pxy.x + (df*pxy.x - sx);
    float ay = m*pxy.y + (df*pxy.y - sy);
    float az = m*pz    + (df*pz    - sz);
    g_Ap[i] = ax; g_Ap[CS+i] = ay; g_Ap[2*CS+i] = az;
    float t = bred(pxy.x*ax + pxy.y*ay + pz*az, s32);
    if (tid == 0) g_pAp[b][cx] = t;
}

// alpha from partials; x += a p; r -= a Ap; rs_{it+1} partials.
// On the last iteration also: pos += dt*x and emit trajectory slice.
__global__ void k_upd(int it, float* __restrict__ out, int step) {
    __shared__ float s32[32];
    __shared__ float s_alpha;
    int tid = threadIdx.x, cx = blockIdx.x, b = blockIdx.y;
    int cur = it & 1;
    int v = cx*VPC + tid;
    int i = b*NVV + v;
    if (tid == 0) {
        float rs = 0.f, pap = 0.f;
        #pragma unroll
        for (int k = 0; k < NCTA; k++) { rs += g_rs[cur][b][k]; pap += g_pAp[b][k]; }
        s_alpha = rs / (pap + 1e-12f);
    }
    __syncthreads();
    float a = s_alpha;
    const float* p = g_pb[cur];
    float xx = g_x[i]        + a*p[i];
    float xy = g_x[CS+i]     + a*p[CS+i];
    float xz = g_x[2*CS+i]   + a*p[2*CS+i];
    float rx = g_r[i]        - a*g_Ap[i];
    float ry = g_r[CS+i]     - a*g_Ap[CS+i];
    float rz = g_r[2*CS+i]   - a*g_Ap[2*CS+i];
    g_x[i] = xx; g_x[CS+i] = xy; g_x[2*CS+i] = xz;
    g_r[i] = rx; g_r[CS+i] = ry; g_r[2*CS+i] = rz;
    float t = bred(rx*rx + ry*ry + rz*rz, s32);
    if (tid == 0) g_rs[cur ^ 1][b][cx] = t;

    if (it == CG_ITERS - 1) {
        float px = g_pos[i]        + DTf*xx;
        float py = g_pos[CS+i]     + DTf*xy;
        float pz = g_pos[2*CS+i]   + DTf*xz;
        g_pos[i] = px; g_pos[CS+i] = py; g_pos[2*CS+i] = pz;
        size_t o = (((size_t)b*NSUB + step)*NVV + v)*3;
        out[o+0] = px; out[o+1] = py; out[o+2] = pz;
    }
}

// ---------------- launch ----------------------------------------------------
extern "C" void kernel_launch(void* const* d_in, const int* in_sizes, int n_in,
                              void* d_out, int out_size) {
    const float* act   = (const float*)d_in[0];
    const float* pos0  = (const float*)d_in[1];
    const float* vel0  = (const float*)d_in[2];
    const float* rlen  = (const float*)d_in[3];
    const float* mass  = (const float*)d_in[4];
    const int*   ei    = (const int*)d_in[5];
    const int*   ej    = (const int*)d_in[6];
    float*       out   = (float*)d_out;

    const int smbytes = NVV*sizeof(float2) + NVV*sizeof(float);   // 96 KB
    static int attr_done = 0;
    if (!attr_done) {
        cudaFuncSetAttribute(k_force, cudaFuncAttributeMaxDynamicSharedMemorySize, smbytes);
        cudaFuncSetAttribute(k_mv,    cudaFuncAttributeMaxDynamicSharedMemorySize, smbytes);
        attr_done = 1;
    }

    k_zero_cnt<<<(NVV+255)/256, 256>>>();
    k_init<<<(CS+255)/256, 256>>>(pos0, vel0);
    k_fill<<<(NEE+255)/256, 256>>>(ei, ej);
    k_sort<<<(NVV+127)/128, 128>>>();
    k_rest<<<dim3(NVV/256, BB), 256>>>(rlen, act);

    dim3 g(NCTA, BB);
    for (int s = 0; s < NSUB; s++) {
        k_force<<<g, TPB, smbytes>>>(mass);
        for (int it = 0; it < CG_ITERS; it++) {
            k_mv <<<g, TPB, smbytes>>>(mass, it);
            k_upd<<<g, TPB>>>(it, out, s);
        }
    }
}